// round 15
// baseline (speedup 1.0000x reference)
#include <cuda_runtime.h>
#include <math.h>

#define BB   2
#define C    128
#define NPT  2048
#define H    4
#define D    32
#define KNN  20
#define C2   256

// ---------------- scratch (device globals; no runtime alloc) ----------------
__device__ float    g_q[BB*H*NPT*D];
__device__ float    g_k[BB*H*NPT*D];
__device__ float    g_v[BB*H*NPT*D];
__device__ float    g_gram[(size_t)BB*NPT*NPT];       // 33.5 MB (L2-resident)
__device__ int      g_idx[BB*NPT*KNN];
__device__ unsigned g_bits[BB*NPT*(NPT/32)];          // knn bitsets
__device__ float    g_av[(size_t)BB*NPT*C];           // (B,N,C)
__device__ float    g_Wh[C2*C2];                      // combined [w1x | w1a@wm]
__device__ float    g_bh[C2];
__device__ float    g_h[(size_t)BB*NPT*C2];           // pre-BN h, (B*N, 2C)
__device__ float    g_sum[C2], g_sumsq[C2];

#define NBW (BB*NPT*(NPT/32))                         // g_bits words
#define NT (NPT/128)                                  // 16 tiles
#define NTRI (NT*(NT+1)/2)                            // 136 tri-tiles per batch
#define GRAM_BLKS (NTRI*BB)                           // 272
#define TOPK_BLKS ((BB*NPT)/8)                        // 512
#define QKV_BLKS  (32*6*BB)                           // 384
#define COMB_BLKS (C2/2)                              // 128
#define FUSEB_BLKS (TOPK_BLKS + QKV_BLKS + COMB_BLKS) // 1024

__device__ __forceinline__ unsigned f2ord(float f){
    unsigned a = __float_as_uint(f);
    return a ^ ((a & 0x80000000u) ? 0xFFFFFFFFu : 0x80000000u);
}

// ================= kernel A: gram only (topk's sole dependency) =================
__global__ __launch_bounds__(256) void k_gram(const float* __restrict__ x){
    __shared__ float S[2*32*132 + 256];
    float (*As)[132] = (float(*)[132])S;
    float (*Bs)[132] = (float(*)[132])(S + 32*132);
    float* xxm = S + 2*32*132;
    float* xxn = xxm + 128;
    int bx = blockIdx.x;
    int tid = threadIdx.x;
    int b = bx / NTRI;
    {
        int lo = bx*964, hi = bx*964 + 964; if (hi > NBW) hi = NBW;
        for (int w = lo + tid; w < hi; w += 256) g_bits[w] = 0u;
    }
    int u = bx % NTRI, ti = 0;
    while (u >= NT - ti){ u -= NT - ti; ti++; }
    int tj = ti + u;
    int n0 = ti*128, m0 = tj*128;
    int tx = tid & 15, ty = tid >> 4;
    const float* xb = x + (size_t)b*C*NPT;
    {
        int col = tid & 127;
        int base0 = (tid < 128) ? m0 : n0;
        float s = 0.f;
        #pragma unroll 4
        for (int c = 0; c < C; c++){ float v = xb[(size_t)c*NPT + base0 + col]; s = fmaf(v,v,s); }
        if (tid < 128) xxm[col] = s; else xxn[col] = s;
    }
    float acc[8][8] = {};
    for (int k0 = 0; k0 < C; k0 += 32){
        #pragma unroll
        for (int it = 0; it < 16; it++){
            int i = tid & 127, kk = (tid >> 7) + it*2;
            As[kk][i] = xb[(size_t)(k0+kk)*NPT + n0 + i];
            Bs[kk][i] = xb[(size_t)(k0+kk)*NPT + m0 + i];
        }
        __syncthreads();
        #pragma unroll
        for (int kk = 0; kk < 32; kk++){
            float4 a0 = *(const float4*)&As[kk][ty*8];
            float4 a1 = *(const float4*)&As[kk][ty*8+4];
            float4 b0 = *(const float4*)&Bs[kk][tx*8];
            float4 b1 = *(const float4*)&Bs[kk][tx*8+4];
            float a[8] = {a0.x,a0.y,a0.z,a0.w,a1.x,a1.y,a1.z,a1.w};
            float bb[8] = {b0.x,b0.y,b0.z,b0.w,b1.x,b1.y,b1.z,b1.w};
            #pragma unroll
            for (int i = 0; i < 8; i++)
                #pragma unroll
                for (int j = 0; j < 8; j++)
                    acc[i][j] = fmaf(a[i], bb[j], acc[i][j]);
        }
        __syncthreads();
    }
    float* gp = g_gram + (size_t)b*NPT*NPT;
    #pragma unroll
    for (int i = 0; i < 8; i++){
        int n = n0 + ty*8 + i;
        #pragma unroll
        for (int j = 0; j < 8; j++){
            int m = m0 + tx*8 + j;
            gp[(size_t)n*NPT + m] = 2.f*acc[i][j] - xxm[tx*8+j];
        }
    }
    if (ti != tj){
        float (*Ts)[36] = (float(*)[36])S;
        #pragma unroll
        for (int c = 0; c < 4; c++){
            __syncthreads();
            if ((ty >> 2) == c){
                #pragma unroll
                for (int i = 0; i < 8; i++){
                    int nl = ty*8 + i;
                    float xn = xxn[nl];
                    #pragma unroll
                    for (int j = 0; j < 8; j++)
                        Ts[tx*8 + j][nl - c*32] = 2.f*acc[i][j] - xn;
                }
            }
            __syncthreads();
            int r = tid >> 1;
            int cl = (tid & 1)*16;
            #pragma unroll
            for (int q = 0; q < 4; q++){
                float4 t4 = *(const float4*)&Ts[r][cl + q*4];
                *(float4*)&gp[(size_t)(m0 + r)*NPT + n0 + c*32 + cl + q*4] = t4;
            }
        }
    }
}

// ================= kernel B: topk | qkv | combine (co-resident blocks) =================
__global__ __launch_bounds__(256) void k_fusedB(
    const float* __restrict__ x,
    const float* __restrict__ wq, const float* __restrict__ bq,
    const float* __restrict__ wk, const float* __restrict__ bk,
    const float* __restrict__ wv, const float* __restrict__ bv,
    const float* __restrict__ w1, const float* __restrict__ b1,
    const float* __restrict__ wm, const float* __restrict__ bm)
{
    __shared__ float SU[4160];
    int bx = blockIdx.x;
    int tid = threadIdx.x;

    if (bx < TOPK_BLKS){
        // ---------------- topk: radix select, one row per warp ----------------
        int wid = tid >> 5, lane = tid & 31;
        int row = bx*8 + wid;
        const float4* g4 = (const float4*)(g_gram + (size_t)row*NPT);
        int*      hist  = (int*)SU;
        unsigned* candV = (unsigned*)(SU + 2048);
        int*      candI = (int*)(SU + 3072);
        int*      misc  = (int*)(SU + 4096);
        int* h = hist + wid*256;

        for (int i = lane; i < 256; i += 32) h[i] = 0;
        if (lane == 0) misc[wid] = 0;
        __syncwarp();

        #pragma unroll 4
        for (int t = 0; t < 16; t++){
            float4 f = g4[t*32 + lane];
            atomicAdd(&h[f2ord(f.x) >> 24], 1);
            atomicAdd(&h[f2ord(f.y) >> 24], 1);
            atomicAdd(&h[f2ord(f.z) >> 24], 1);
            atomicAdd(&h[f2ord(f.w) >> 24], 1);
        }
        __syncwarp();
        {
            int c[8]; int base = lane*8; int gsum = 0;
            #pragma unroll
            for (int j = 0; j < 8; j++){ c[j] = h[base+j]; gsum += c[j]; }
            int acc = gsum;
            #pragma unroll
            for (int off = 1; off < 32; off <<= 1){
                int o = __shfl_down_sync(0xffffffffu, acc, off);
                if (lane + off < 32) acc += o;
            }
            int suf = acc - gsum;
            #pragma unroll
            for (int j = 7; j >= 0; j--){
                if (suf < KNN && suf + c[j] >= KNN){ misc[8+wid] = base+j; misc[16+wid] = KNN - suf; }
                suf += c[j];
            }
        }
        __syncwarp();
        unsigned T1 = (unsigned)misc[8+wid]; int k1 = misc[16+wid];

        for (int i = lane; i < 256; i += 32) h[i] = 0;
        __syncwarp();
        #pragma unroll 4
        for (int t = 0; t < 16; t++){
            float4 f = g4[t*32 + lane];
            unsigned a;
            a = f2ord(f.x); if ((a >> 24) == T1) atomicAdd(&h[(a >> 16) & 255], 1);
            a = f2ord(f.y); if ((a >> 24) == T1) atomicAdd(&h[(a >> 16) & 255], 1);
            a = f2ord(f.z); if ((a >> 24) == T1) atomicAdd(&h[(a >> 16) & 255], 1);
            a = f2ord(f.w); if ((a >> 24) == T1) atomicAdd(&h[(a >> 16) & 255], 1);
        }
        __syncwarp();
        {
            int c[8]; int base = lane*8; int gsum = 0;
            #pragma unroll
            for (int j = 0; j < 8; j++){ c[j] = h[base+j]; gsum += c[j]; }
            int acc = gsum;
            #pragma unroll
            for (int off = 1; off < 32; off <<= 1){
                int o = __shfl_down_sync(0xffffffffu, acc, off);
                if (lane + off < 32) acc += o;
            }
            int suf = acc - gsum;
            #pragma unroll
            for (int j = 7; j >= 0; j--){
                if (suf < k1 && suf + c[j] >= k1){ misc[24+wid] = base+j; }
                suf += c[j];
            }
        }
        __syncwarp();
        unsigned thr = (T1 << 8) | (unsigned)misc[24+wid];

        #pragma unroll 4
        for (int t = 0; t < 16; t++){
            float4 f = g4[t*32 + lane];
            int base = (t*32 + lane)*4;
            unsigned a;
            a = f2ord(f.x);
            if ((a >> 16) >= thr){ int p = atomicAdd(&misc[wid],1); if (p<128){ candV[wid*128+p]=a; candI[wid*128+p]=base+0; } }
            a = f2ord(f.y);
            if ((a >> 16) >= thr){ int p = atomicAdd(&misc[wid],1); if (p<128){ candV[wid*128+p]=a; candI[wid*128+p]=base+1; } }
            a = f2ord(f.z);
            if ((a >> 16) >= thr){ int p = atomicAdd(&misc[wid],1); if (p<128){ candV[wid*128+p]=a; candI[wid*128+p]=base+2; } }
            a = f2ord(f.w);
            if ((a >> 16) >= thr){ int p = atomicAdd(&misc[wid],1); if (p<128){ candV[wid*128+p]=a; candI[wid*128+p]=base+3; } }
        }
        __syncwarp();

        int cc = min(misc[wid], 128);
        for (int r = 0; r < KNN; r++){
            unsigned bv = 0; int bi = 0x7fffffff;
            for (int i = lane; i < cc; i += 32){
                unsigned vv = candV[wid*128+i];
                if (vv > bv || (vv == bv && candI[wid*128+i] < bi)){ bv = vv; bi = candI[wid*128+i]; }
            }
            unsigned wm2 = __reduce_max_sync(0xffffffffu, bv);
            unsigned wiu = (bv == wm2) ? (unsigned)bi : 0x7fffffffu;
            int wi = (int)__reduce_min_sync(0xffffffffu, wiu);
            for (int i = lane; i < cc; i += 32)
                if (candV[wid*128+i] == wm2 && candI[wid*128+i] == wi){ candV[wid*128+i] = 0u; candI[wid*128+i] = 0x7fffffff; }
            if (lane == 0){
                g_idx[row*KNN + r] = wi;
                atomicOr(&g_bits[(size_t)row*(NPT/32) + (wi >> 5)], 1u << (wi & 31));
            }
        }
    } else if (bx < TOPK_BLKS + QKV_BLKS){
        // ---------------- qkv ----------------
        float (*As)[65] = (float(*)[65])SU;
        float (*Ws)[65] = (float(*)[65])(SU + 32*65);
        int i0 = bx - TOPK_BLKS;
        int n0  = (i0 & 31)*64;
        int oc0 = ((i0 >> 5) % 6)*64;
        int b   = i0 / 192;
        int tx = tid & 15, ty = tid >> 4;
        float acc[4][4] = {};
        for (int k0 = 0; k0 < C; k0 += 32){
            #pragma unroll
            for (int it = 0; it < 8; it++){
                int i = tid & 63, kk = (tid >> 6) + it*4;
                As[kk][i] = x[(size_t)b*C*NPT + (size_t)(k0+kk)*NPT + n0 + i];
            }
            #pragma unroll
            for (int it = 0; it < 8; it++){
                int kk = tid & 31, j = (tid >> 5) + it*8;
                int oc = oc0 + j;
                const float* wp = (oc < C) ? wq : (oc < 2*C ? wk : wv);
                int ocl = oc & (C-1);
                Ws[kk][j] = wp[ocl*C + k0 + kk];
            }
            __syncthreads();
            #pragma unroll
            for (int kk = 0; kk < 32; kk++){
                float a[4], w[4];
                #pragma unroll
                for (int u = 0; u < 4; u++){ a[u] = As[kk][ty*4+u]; w[u] = Ws[kk][tx*4+u]; }
                #pragma unroll
                for (int i = 0; i < 4; i++)
                    #pragma unroll
                    for (int j = 0; j < 4; j++)
                        acc[i][j] = fmaf(a[i], w[j], acc[i][j]);
            }
            __syncthreads();
        }
        #pragma unroll
        for (int i = 0; i < 4; i++){
            int n = n0 + ty*4 + i;
            #pragma unroll
            for (int j = 0; j < 4; j++){
                int oc = oc0 + tx*4 + j;
                int t = oc >> 7, ocl = oc & (C-1);
                int h = ocl >> 5, d = ocl & 31;
                float bias = (t==0 ? bq : (t==1 ? bk : bv))[ocl];
                float* dst = (t==0 ? g_q : (t==1 ? g_k : g_v));
                dst[(((size_t)b*H + h)*NPT + n)*D + d] = acc[i][j] + bias;
            }
        }
    } else {
        // ---------------- combine ----------------
        float* red = SU;
        int half = tid >> 7;
        int c = tid & 127;
        int oc = (bx - TOPK_BLKS - QKV_BLKS)*2 + half;
        if (c == 0){ g_sum[oc] = 0.f; g_sumsq[oc] = 0.f; }
        float s = 0.f;
        for (int c2 = 0; c2 < C; c2++)
            s = fmaf(w1[oc*C2 + C + c2], wm[c2*C + c], s);
        g_Wh[oc*C2 + C + c] = s;
        g_Wh[oc*C2 + c] = w1[oc*C2 + c];
        red[tid] = w1[oc*C2 + C + c] * bm[c];
        __syncthreads();
        for (int s2 = 64; s2; s2 >>= 1){
            if (c < s2) red[half*128 + c] += red[half*128 + c + s2];
            __syncthreads();
        }
        if (c == 0) g_bh[oc] = b1[oc] + red[half*128];
    }
}

// ---------------- K4: mutual-mask + sparse attention (warp = head) ----------------
__global__ __launch_bounds__(128) void k_attn(){
    int row = blockIdx.x;
    int b = row >> 11, n = row & (NPT-1);
    int tid = threadIdx.x;
    int h = tid >> 5, lane = tid & 31;
    __shared__ int adj[32]; __shared__ int scnt;
    __shared__ float sk[H][KNN][33];
    __shared__ float sv[H][KNN][33];
    __shared__ float sq[H][32];
    __shared__ float sp[H][32];
    if (tid < 32){
        adj[tid] = 0;
        __syncwarp();
        int m = 0; bool ok = false;
        if (tid < KNN){
            m = g_idx[row*KNN + tid];
            ok = (g_bits[(size_t)(b*NPT + m)*(NPT/32) + (n >> 5)] >> (n & 31)) & 1u;
        }
        unsigned ball = __ballot_sync(0xffffffffu, ok);
        int pos = __popc(ball & ((1u << tid) - 1u));
        if (ok) adj[pos] = m;
        if (tid == 0) scnt = __popc(ball);
    }
    __syncthreads();
    int cnt = scnt;
    size_t hb = ((size_t)(b*H + h))*NPT*D;
    sq[h][lane] = g_q[hb + (size_t)n*D + lane];
    #pragma unroll
    for (int j = 0; j < KNN; j++){
        int m = adj[j];
        sk[h][j][lane] = g_k[hb + (size_t)m*D + lane];
        sv[h][j][lane] = g_v[hb + (size_t)m*D + lane];
    }
    __syncwarp();
    float s = -3.4e38f;
    if (lane < cnt){
        float a = 0.f;
        #pragma unroll 8
        for (int d = 0; d < 32; d++) a = fmaf(sq[h][d], sk[h][lane][d], a);
        s = a * 0.17677669529663687f;
    }
    float mx = s;
    #pragma unroll
    for (int off = 16; off; off >>= 1) mx = fmaxf(mx, __shfl_xor_sync(0xffffffffu, mx, off));
    float e = (lane < cnt) ? expf(s - mx) : 0.f;
    float se = e;
    #pragma unroll
    for (int off = 16; off; off >>= 1) se += __shfl_xor_sync(0xffffffffu, se, off);
    sp[h][lane] = e / se;
    __syncwarp();
    float acc = 0.f;
    #pragma unroll
    for (int j = 0; j < KNN; j++)
        acc = fmaf(sp[h][j], sv[h][j][lane], acc);
    g_av[(size_t)row*C + h*D + lane] = acc;
}

// ---------------- K5b: h = Wh @ [x; av] + bh  (double-buffered smem, 1 sync/chunk) ----------------
__global__ __launch_bounds__(256) void k_hgemm(const float* __restrict__ x){
    __shared__ float As[2][32][68], Ws[2][32][68];    // 69.6 KB
    __shared__ float cs[64], cq[64];
    int r0 = blockIdx.x*64, oc0 = blockIdx.y*64;
    int b = r0 / NPT, n0 = r0 % NPT;
    int tid = threadIdx.x, tx = tid & 15, ty = tid >> 4;
    if (tid < 64){ cs[tid] = 0.f; cq[tid] = 0.f; }
    float acc[4][4] = {};
    float fA[8], fW[8];

    #define HG_LOADA(k0) do{ \
        if ((k0) < C){ \
            _Pragma("unroll") \
            for (int it = 0; it < 8; it++) \
                fA[it] = x[(size_t)b*C*NPT + (size_t)((k0)+(tid>>6)+it*4)*NPT + n0 + (tid&63)]; \
        } else { \
            _Pragma("unroll") \
            for (int it = 0; it < 8; it++) \
                fA[it] = g_av[(size_t)(r0+(tid>>5)+it*8)*C + ((k0)-C) + (tid&31)]; \
        } } while(0)
    #define HG_LOADW(k0) do{ \
        _Pragma("unroll") \
        for (int it = 0; it < 8; it++) \
            fW[it] = g_Wh[(size_t)(oc0+(tid>>5)+it*8)*C2 + (k0) + (tid&31)]; } while(0)
    #define HG_STORE(k0, bf) do{ \
        if ((k0) < C){ \
            _Pragma("unroll") \
            for (int it = 0; it < 8; it++) As[bf][(tid>>6)+it*4][tid&63] = fA[it]; \
        } else { \
            _Pragma("unroll") \
            for (int it = 0; it < 8; it++) As[bf][tid&31][(tid>>5)+it*8] = fA[it]; \
        } \
        _Pragma("unroll") \
        for (int it = 0; it < 8; it++) Ws[bf][tid&31][(tid>>5)+it*8] = fW[it]; } while(0)

    HG_LOADA(0); HG_LOADW(0);
    HG_STORE(0, 0);
    __syncthreads();
    #pragma unroll
    for (int kc = 0; kc < 8; kc++){
        int buf = kc & 1;
        if (kc < 7){ HG_LOADA((kc+1)*32); HG_LOADW((kc+1)*32); }
        #pragma unroll
        for (int kk = 0; kk < 32; kk++){
            float4 a4 = *(const float4*)&As[buf][kk][ty*4];
            float4 w4 = *(const float4*)&Ws[buf][kk][tx*4];
            float a[4] = {a4.x,a4.y,a4.z,a4.w};
            float w[4] = {w4.x,w4.y,w4.z,w4.w};
            #pragma unroll
            for (int i = 0; i < 4; i++)
                #pragma unroll
                for (int j = 0; j < 4; j++)
                    acc[i][j] = fmaf(a[i], w[j], acc[i][j]);
        }
        if (kc < 7) HG_STORE((kc+1)*32, buf^1);
        __syncthreads();
    }
    #undef HG_LOADA
    #undef HG_LOADW
    #undef HG_STORE

    float hs[4] = {}, hq[4] = {};
    #pragma unroll
    for (int i = 0; i < 4; i++){
        int r = r0 + ty*4 + i;
        #pragma unroll
        for (int j = 0; j < 4; j++){
            int oc = oc0 + tx*4 + j;
            float hv = acc[i][j] + g_bh[oc];
            g_h[(size_t)r*C2 + oc] = hv;
            hs[j] += hv; hq[j] = fmaf(hv, hv, hq[j]);
        }
    }
    #pragma unroll
    for (int j = 0; j < 4; j++){
        atomicAdd(&cs[tx*4+j], hs[j]);
        atomicAdd(&cq[tx*4+j], hq[j]);
    }
    __syncthreads();
    if (tid < 64){
        atomicAdd(&g_sum[oc0 + tid],   cs[tid]);
        atomicAdd(&g_sumsq[oc0 + tid], cq[tid]);
    }
}

// ---------------- K5d: out = x + w2 @ relu(bn(h)) + b2  (double-buffered, 64x32 tiles) ----------------
__global__ __launch_bounds__(256) void k_out(const float* __restrict__ x,
                                             const float* __restrict__ w2,
                                             const float* __restrict__ b2,
                                             const float* __restrict__ gamma,
                                             const float* __restrict__ beta,
                                             float* __restrict__ out){
    __shared__ float As[2][32][68], Ws[2][32][36];
    __shared__ float ssc[C2], ssh[C2];
    int r0 = blockIdx.x*64, c0 = blockIdx.y*32;
    int b = r0 / NPT, n0 = r0 % NPT;
    int tid = threadIdx.x, tx = tid & 15, ty = tid >> 4;
    {
        int oc = tid;
        float inv = 1.f / (float)(BB*NPT);
        float mean = g_sum[oc] * inv;
        float var  = g_sumsq[oc] * inv - mean*mean;
        float rstd = rsqrtf(var + 1e-5f);
        float sc = rstd * gamma[oc];
        ssc[oc] = sc;
        ssh[oc] = beta[oc] - mean * sc;
    }
    __syncthreads();

    float acc[4][2] = {};
    float fH[8], fW[4];

    #define KO_LOAD(k0) do{ \
        _Pragma("unroll") \
        for (int it = 0; it < 8; it++) \
            fH[it] = g_h[(size_t)(r0+(tid>>5)+it*8)*C2 + (k0) + (tid&31)]; \
        _Pragma("unroll") \
        for (int it = 0; it < 4; it++) \
            fW[it] = w2[(size_t)(c0+(tid>>5)+it*8)*C2 + (k0) + (tid&31)]; } while(0)
    #define KO_STORE(k0, bf) do{ \
        int kk = tid & 31; \
        float sc = ssc[(k0)+kk], sh = ssh[(k0)+kk]; \
        _Pragma("unroll") \
        for (int it = 0; it < 8; it++) \
            As[bf][kk][(tid>>5)+it*8] = fmaxf(fmaf(fH[it], sc, sh), 0.f); \
        _Pragma("unroll") \
        for (int it = 0; it < 4; it++) \
            Ws[bf][kk][(tid>>5)+it*8] = fW[it]; } while(0)

    KO_LOAD(0);
    KO_STORE(0, 0);
    __syncthreads();
    #pragma unroll
    for (int kc = 0; kc < 8; kc++){
        int buf = kc & 1;
        if (kc < 7) KO_LOAD((kc+1)*32);
        #pragma unroll
        for (int kk = 0; kk < 32; kk++){
            float4 a4 = *(const float4*)&As[buf][kk][ty*4];
            float2 w2v = *(const float2*)&Ws[buf][kk][tx*2];
            float a[4] = {a4.x,a4.y,a4.z,a4.w};
            #pragma unroll
            for (int i = 0; i < 4; i++){
                acc[i][0] = fmaf(a[i], w2v.x, acc[i][0]);
                acc[i][1] = fmaf(a[i], w2v.y, acc[i][1]);
            }
        }
        if (kc < 7) KO_STORE((kc+1)*32, buf^1);
        __syncthreads();
    }
    #undef KO_LOAD
    #undef KO_STORE

    #pragma unroll
    for (int i = 0; i < 4; i++){
        int n = n0 + ty*4 + i;
        #pragma unroll
        for (int j = 0; j < 2; j++){
            int c = c0 + tx*2 + j;
            size_t idx = (size_t)b*C*NPT + (size_t)c*NPT + n;
            out[idx] = x[idx] + b2[c] + acc[i][j];
        }
    }
}

// ---------------- launch ----------------
extern "C" void kernel_launch(void* const* d_in, const int* in_sizes, int n_in,
                              void* d_out, int out_size){
    const float* x     = (const float*)d_in[0];
    const float* wq    = (const float*)d_in[1];
    const float* bq    = (const float*)d_in[2];
    const float* wk    = (const float*)d_in[3];
    const float* bk    = (const float*)d_in[4];
    const float* wv    = (const float*)d_in[5];
    const float* bv    = (const float*)d_in[6];
    const float* wm    = (const float*)d_in[7];
    const float* bm    = (const float*)d_in[8];
    const float* w1    = (const float*)d_in[9];
    const float* b1    = (const float*)d_in[10];
    const float* gamma = (const float*)d_in[11];
    const float* beta  = (const float*)d_in[12];
    const float* w2    = (const float*)d_in[13];
    const float* b2    = (const float*)d_in[14];
    float* out = (float*)d_out;

    cudaFuncSetAttribute(k_hgemm, cudaFuncAttributeMaxDynamicSharedMemorySize, 0);

    k_gram<<<GRAM_BLKS, 256>>>(x);
    k_fusedB<<<FUSEB_BLKS, 256>>>(x, wq, bq, wk, bk, wv, bv, w1, b1, wm, bm);
    k_attn<<<BB*NPT, 128>>>();
    k_hgemm<<<dim3((BB*NPT)/64, C2/64), 256>>>(x);
    k_out<<<dim3((BB*NPT)/64, C/32), 256>>>(x, w2, b2, gamma, beta, out);
}

// round 16
// speedup vs baseline: 1.0496x; 1.0496x over previous
#include <cuda_runtime.h>
#include <math.h>

#define BB   2
#define C    128
#define NPT  2048
#define H    4
#define D    32
#define KNN  20
#define C2   256

// ---------------- scratch (device globals; no runtime alloc) ----------------
__device__ float    g_q[BB*H*NPT*D];
__device__ float    g_k[BB*H*NPT*D];
__device__ float    g_v[BB*H*NPT*D];
__device__ float    g_gram[(size_t)BB*NPT*NPT];       // 33.5 MB (L2-resident)
__device__ int      g_idx[BB*NPT*KNN];
__device__ unsigned g_bits[BB*NPT*(NPT/32)];          // knn bitsets
__device__ float    g_av[(size_t)BB*NPT*C];           // (B,N,C)
__device__ float    g_Wh[C2*C2];                      // combined [w1x | w1a@wm]
__device__ float    g_bh[C2];
__device__ float    g_h[(size_t)BB*NPT*C2];           // pre-BN h, (B*N, 2C)
__device__ float    g_sum[C2], g_sumsq[C2];

#define NBW (BB*NPT*(NPT/32))                         // g_bits words
#define NT (NPT/128)                                  // 16 tiles
#define NTRI (NT*(NT+1)/2)                            // 136 tri-tiles per batch
#define GRAM_BLKS (NTRI*BB)                           // 272
#define TOPK_BLKS ((BB*NPT)/8)                        // 512
#define QKV_BLKS  (32*6*BB)                           // 384
#define COMB_BLKS (C2/2)                              // 128
#define FUSEB_BLKS (TOPK_BLKS + QKV_BLKS + COMB_BLKS) // 1024

__device__ __forceinline__ unsigned f2ord(float f){
    unsigned a = __float_as_uint(f);
    return a ^ ((a & 0x80000000u) ? 0xFFFFFFFFu : 0x80000000u);
}

// ================= kernel A: gram only (topk's sole dependency) =================
__global__ __launch_bounds__(256) void k_gram(const float* __restrict__ x){
    __shared__ float S[2*32*132 + 256];
    float (*As)[132] = (float(*)[132])S;
    float (*Bs)[132] = (float(*)[132])(S + 32*132);
    float* xxm = S + 2*32*132;
    float* xxn = xxm + 128;
    int bx = blockIdx.x;
    int tid = threadIdx.x;
    int b = bx / NTRI;
    {
        int lo = bx*964, hi = bx*964 + 964; if (hi > NBW) hi = NBW;
        for (int w = lo + tid; w < hi; w += 256) g_bits[w] = 0u;
    }
    int u = bx % NTRI, ti = 0;
    while (u >= NT - ti){ u -= NT - ti; ti++; }
    int tj = ti + u;
    int n0 = ti*128, m0 = tj*128;
    int tx = tid & 15, ty = tid >> 4;
    const float* xb = x + (size_t)b*C*NPT;
    {
        int col = tid & 127;
        int base0 = (tid < 128) ? m0 : n0;
        float s = 0.f;
        #pragma unroll 4
        for (int c = 0; c < C; c++){ float v = xb[(size_t)c*NPT + base0 + col]; s = fmaf(v,v,s); }
        if (tid < 128) xxm[col] = s; else xxn[col] = s;
    }
    float acc[8][8] = {};
    for (int k0 = 0; k0 < C; k0 += 32){
        #pragma unroll
        for (int it = 0; it < 16; it++){
            int i = tid & 127, kk = (tid >> 7) + it*2;
            As[kk][i] = xb[(size_t)(k0+kk)*NPT + n0 + i];
            Bs[kk][i] = xb[(size_t)(k0+kk)*NPT + m0 + i];
        }
        __syncthreads();
        #pragma unroll
        for (int kk = 0; kk < 32; kk++){
            float4 a0 = *(const float4*)&As[kk][ty*8];
            float4 a1 = *(const float4*)&As[kk][ty*8+4];
            float4 b0 = *(const float4*)&Bs[kk][tx*8];
            float4 b1 = *(const float4*)&Bs[kk][tx*8+4];
            float a[8] = {a0.x,a0.y,a0.z,a0.w,a1.x,a1.y,a1.z,a1.w};
            float bb[8] = {b0.x,b0.y,b0.z,b0.w,b1.x,b1.y,b1.z,b1.w};
            #pragma unroll
            for (int i = 0; i < 8; i++)
                #pragma unroll
                for (int j = 0; j < 8; j++)
                    acc[i][j] = fmaf(a[i], bb[j], acc[i][j]);
        }
        __syncthreads();
    }
    float* gp = g_gram + (size_t)b*NPT*NPT;
    #pragma unroll
    for (int i = 0; i < 8; i++){
        int n = n0 + ty*8 + i;
        #pragma unroll
        for (int j = 0; j < 8; j++){
            int m = m0 + tx*8 + j;
            gp[(size_t)n*NPT + m] = 2.f*acc[i][j] - xxm[tx*8+j];
        }
    }
    if (ti != tj){
        float (*Ts)[36] = (float(*)[36])S;
        #pragma unroll
        for (int c = 0; c < 4; c++){
            __syncthreads();
            if ((ty >> 2) == c){
                #pragma unroll
                for (int i = 0; i < 8; i++){
                    int nl = ty*8 + i;
                    float xn = xxn[nl];
                    #pragma unroll
                    for (int j = 0; j < 8; j++)
                        Ts[tx*8 + j][nl - c*32] = 2.f*acc[i][j] - xn;
                }
            }
            __syncthreads();
            int r = tid >> 1;
            int cl = (tid & 1)*16;
            #pragma unroll
            for (int q = 0; q < 4; q++){
                float4 t4 = *(const float4*)&Ts[r][cl + q*4];
                *(float4*)&gp[(size_t)(m0 + r)*NPT + n0 + c*32 + cl + q*4] = t4;
            }
        }
    }
}

// ================= kernel B: topk | qkv | combine (co-resident blocks) =================
__global__ __launch_bounds__(256) void k_fusedB(
    const float* __restrict__ x,
    const float* __restrict__ wq, const float* __restrict__ bq,
    const float* __restrict__ wk, const float* __restrict__ bk,
    const float* __restrict__ wv, const float* __restrict__ bv,
    const float* __restrict__ w1, const float* __restrict__ b1,
    const float* __restrict__ wm, const float* __restrict__ bm)
{
    __shared__ float SU[4160];
    int bx = blockIdx.x;
    int tid = threadIdx.x;

    if (bx < TOPK_BLKS){
        // ---------------- topk: radix select, one row per warp ----------------
        int wid = tid >> 5, lane = tid & 31;
        int row = bx*8 + wid;
        const float4* g4 = (const float4*)(g_gram + (size_t)row*NPT);
        int*      hist  = (int*)SU;
        unsigned* candV = (unsigned*)(SU + 2048);
        int*      candI = (int*)(SU + 3072);
        int*      misc  = (int*)(SU + 4096);
        int* h = hist + wid*256;

        for (int i = lane; i < 256; i += 32) h[i] = 0;
        if (lane == 0) misc[wid] = 0;
        __syncwarp();

        #pragma unroll 4
        for (int t = 0; t < 16; t++){
            float4 f = g4[t*32 + lane];
            atomicAdd(&h[f2ord(f.x) >> 24], 1);
            atomicAdd(&h[f2ord(f.y) >> 24], 1);
            atomicAdd(&h[f2ord(f.z) >> 24], 1);
            atomicAdd(&h[f2ord(f.w) >> 24], 1);
        }
        __syncwarp();
        {
            int c[8]; int base = lane*8; int gsum = 0;
            #pragma unroll
            for (int j = 0; j < 8; j++){ c[j] = h[base+j]; gsum += c[j]; }
            int acc = gsum;
            #pragma unroll
            for (int off = 1; off < 32; off <<= 1){
                int o = __shfl_down_sync(0xffffffffu, acc, off);
                if (lane + off < 32) acc += o;
            }
            int suf = acc - gsum;
            #pragma unroll
            for (int j = 7; j >= 0; j--){
                if (suf < KNN && suf + c[j] >= KNN){ misc[8+wid] = base+j; misc[16+wid] = KNN - suf; }
                suf += c[j];
            }
        }
        __syncwarp();
        unsigned T1 = (unsigned)misc[8+wid]; int k1 = misc[16+wid];

        for (int i = lane; i < 256; i += 32) h[i] = 0;
        __syncwarp();
        #pragma unroll 4
        for (int t = 0; t < 16; t++){
            float4 f = g4[t*32 + lane];
            unsigned a;
            a = f2ord(f.x); if ((a >> 24) == T1) atomicAdd(&h[(a >> 16) & 255], 1);
            a = f2ord(f.y); if ((a >> 24) == T1) atomicAdd(&h[(a >> 16) & 255], 1);
            a = f2ord(f.z); if ((a >> 24) == T1) atomicAdd(&h[(a >> 16) & 255], 1);
            a = f2ord(f.w); if ((a >> 24) == T1) atomicAdd(&h[(a >> 16) & 255], 1);
        }
        __syncwarp();
        {
            int c[8]; int base = lane*8; int gsum = 0;
            #pragma unroll
            for (int j = 0; j < 8; j++){ c[j] = h[base+j]; gsum += c[j]; }
            int acc = gsum;
            #pragma unroll
            for (int off = 1; off < 32; off <<= 1){
                int o = __shfl_down_sync(0xffffffffu, acc, off);
                if (lane + off < 32) acc += o;
            }
            int suf = acc - gsum;
            #pragma unroll
            for (int j = 7; j >= 0; j--){
                if (suf < k1 && suf + c[j] >= k1){ misc[24+wid] = base+j; }
                suf += c[j];
            }
        }
        __syncwarp();
        unsigned thr = (T1 << 8) | (unsigned)misc[24+wid];

        #pragma unroll 4
        for (int t = 0; t < 16; t++){
            float4 f = g4[t*32 + lane];
            int base = (t*32 + lane)*4;
            unsigned a;
            a = f2ord(f.x);
            if ((a >> 16) >= thr){ int p = atomicAdd(&misc[wid],1); if (p<128){ candV[wid*128+p]=a; candI[wid*128+p]=base+0; } }
            a = f2ord(f.y);
            if ((a >> 16) >= thr){ int p = atomicAdd(&misc[wid],1); if (p<128){ candV[wid*128+p]=a; candI[wid*128+p]=base+1; } }
            a = f2ord(f.z);
            if ((a >> 16) >= thr){ int p = atomicAdd(&misc[wid],1); if (p<128){ candV[wid*128+p]=a; candI[wid*128+p]=base+2; } }
            a = f2ord(f.w);
            if ((a >> 16) >= thr){ int p = atomicAdd(&misc[wid],1); if (p<128){ candV[wid*128+p]=a; candI[wid*128+p]=base+3; } }
        }
        __syncwarp();

        int cc = min(misc[wid], 128);
        for (int r = 0; r < KNN; r++){
            unsigned bv = 0; int bi = 0x7fffffff;
            for (int i = lane; i < cc; i += 32){
                unsigned vv = candV[wid*128+i];
                if (vv > bv || (vv == bv && candI[wid*128+i] < bi)){ bv = vv; bi = candI[wid*128+i]; }
            }
            unsigned wm2 = __reduce_max_sync(0xffffffffu, bv);
            unsigned wiu = (bv == wm2) ? (unsigned)bi : 0x7fffffffu;
            int wi = (int)__reduce_min_sync(0xffffffffu, wiu);
            for (int i = lane; i < cc; i += 32)
                if (candV[wid*128+i] == wm2 && candI[wid*128+i] == wi){ candV[wid*128+i] = 0u; candI[wid*128+i] = 0x7fffffff; }
            if (lane == 0){
                g_idx[row*KNN + r] = wi;
                atomicOr(&g_bits[(size_t)row*(NPT/32) + (wi >> 5)], 1u << (wi & 31));
            }
        }
    } else if (bx < TOPK_BLKS + QKV_BLKS){
        // ---------------- qkv ----------------
        float (*As)[65] = (float(*)[65])SU;
        float (*Ws)[65] = (float(*)[65])(SU + 32*65);
        int i0 = bx - TOPK_BLKS;
        int n0  = (i0 & 31)*64;
        int oc0 = ((i0 >> 5) % 6)*64;
        int b   = i0 / 192;
        int tx = tid & 15, ty = tid >> 4;
        float acc[4][4] = {};
        for (int k0 = 0; k0 < C; k0 += 32){
            #pragma unroll
            for (int it = 0; it < 8; it++){
                int i = tid & 63, kk = (tid >> 6) + it*4;
                As[kk][i] = x[(size_t)b*C*NPT + (size_t)(k0+kk)*NPT + n0 + i];
            }
            #pragma unroll
            for (int it = 0; it < 8; it++){
                int kk = tid & 31, j = (tid >> 5) + it*8;
                int oc = oc0 + j;
                const float* wp = (oc < C) ? wq : (oc < 2*C ? wk : wv);
                int ocl = oc & (C-1);
                Ws[kk][j] = wp[ocl*C + k0 + kk];
            }
            __syncthreads();
            #pragma unroll
            for (int kk = 0; kk < 32; kk++){
                float a[4], w[4];
                #pragma unroll
                for (int u = 0; u < 4; u++){ a[u] = As[kk][ty*4+u]; w[u] = Ws[kk][tx*4+u]; }
                #pragma unroll
                for (int i = 0; i < 4; i++)
                    #pragma unroll
                    for (int j = 0; j < 4; j++)
                        acc[i][j] = fmaf(a[i], w[j], acc[i][j]);
            }
            __syncthreads();
        }
        #pragma unroll
        for (int i = 0; i < 4; i++){
            int n = n0 + ty*4 + i;
            #pragma unroll
            for (int j = 0; j < 4; j++){
                int oc = oc0 + tx*4 + j;
                int t = oc >> 7, ocl = oc & (C-1);
                int h = ocl >> 5, d = ocl & 31;
                float bias = (t==0 ? bq : (t==1 ? bk : bv))[ocl];
                float* dst = (t==0 ? g_q : (t==1 ? g_k : g_v));
                dst[(((size_t)b*H + h)*NPT + n)*D + d] = acc[i][j] + bias;
            }
        }
    } else {
        // ---------------- combine ----------------
        float* red = SU;
        int half = tid >> 7;
        int c = tid & 127;
        int oc = (bx - TOPK_BLKS - QKV_BLKS)*2 + half;
        if (c == 0){ g_sum[oc] = 0.f; g_sumsq[oc] = 0.f; }
        float s = 0.f;
        for (int c2 = 0; c2 < C; c2++)
            s = fmaf(w1[oc*C2 + C + c2], wm[c2*C + c], s);
        g_Wh[oc*C2 + C + c] = s;
        g_Wh[oc*C2 + c] = w1[oc*C2 + c];
        red[tid] = w1[oc*C2 + C + c] * bm[c];
        __syncthreads();
        for (int s2 = 64; s2; s2 >>= 1){
            if (c < s2) red[half*128 + c] += red[half*128 + c + s2];
            __syncthreads();
        }
        if (c == 0) g_bh[oc] = b1[oc] + red[half*128];
    }
}

// ---------------- K4: sparse attention, NO K/V smem staging ----------------
__global__ __launch_bounds__(128) void k_attn(){
    int row = blockIdx.x;
    int b = row >> 11, n = row & (NPT-1);
    int tid = threadIdx.x;
    int h = tid >> 5, lane = tid & 31;
    __shared__ int adj[32]; __shared__ int scnt;
    if (tid < 32){
        adj[tid] = 0;
        __syncwarp();
        int m = 0; bool ok = false;
        if (tid < KNN){
            m = g_idx[row*KNN + tid];
            ok = (g_bits[(size_t)(b*NPT + m)*(NPT/32) + (n >> 5)] >> (n & 31)) & 1u;
        }
        unsigned ball = __ballot_sync(0xffffffffu, ok);
        int pos = __popc(ball & ((1u << tid) - 1u));
        if (ok) adj[pos] = m;
        if (tid == 0) scnt = __popc(ball);
    }
    __syncthreads();
    int cnt = scnt;
    size_t hb = ((size_t)(b*H + h))*NPT*D;
    float ql = g_q[hb + (size_t)n*D + lane];

    // score: lane j owns neighbor j; direct float4 loads of K row, q via shfl
    int mj = adj[lane];                                   // lanes >= cnt read 0 (valid row)
    const float4* kr = (const float4*)&g_k[hb + (size_t)mj*D];
    float dot = 0.f;
    #pragma unroll
    for (int t = 0; t < 8; t++){
        float4 kv = kr[t];
        dot = fmaf(__shfl_sync(0xffffffffu, ql, 4*t+0), kv.x, dot);
        dot = fmaf(__shfl_sync(0xffffffffu, ql, 4*t+1), kv.y, dot);
        dot = fmaf(__shfl_sync(0xffffffffu, ql, 4*t+2), kv.z, dot);
        dot = fmaf(__shfl_sync(0xffffffffu, ql, 4*t+3), kv.w, dot);
    }
    float s = (lane < cnt) ? dot * 0.17677669529663687f : -3.4e38f;
    float mx = s;
    #pragma unroll
    for (int off = 16; off; off >>= 1) mx = fmaxf(mx, __shfl_xor_sync(0xffffffffu, mx, off));
    float e = (lane < cnt) ? expf(s - mx) : 0.f;
    float se = e;
    #pragma unroll
    for (int off = 16; off; off >>= 1) se += __shfl_xor_sync(0xffffffffu, se, off);
    float p = e / se;                                     // 0 for lane >= cnt

    // AV: lane = d; direct V gathers, p via shfl (fixed trip count -> all loads in flight)
    float acc = 0.f;
    #pragma unroll
    for (int j = 0; j < KNN; j++){
        float pj = __shfl_sync(0xffffffffu, p, j);
        int m = adj[j];
        acc = fmaf(pj, g_v[hb + (size_t)m*D + lane], acc);
    }
    g_av[(size_t)row*C + h*D + lane] = acc;
}

// ---------------- K5b: h = Wh @ [x; av] + bh  (reg prefetch + LDS.128) ----------------
__global__ __launch_bounds__(256) void k_hgemm(const float* __restrict__ x){
    __shared__ float As[32][68], Ws[32][68];
    __shared__ float cs[64], cq[64];
    int r0 = blockIdx.x*64, oc0 = blockIdx.y*64;
    int b = r0 / NPT, n0 = r0 % NPT;
    int tid = threadIdx.x, tx = tid & 15, ty = tid >> 4;
    if (tid < 64){ cs[tid] = 0.f; cq[tid] = 0.f; }
    float acc[4][4] = {};
    float fA[8], fW[8];

    #define HG_LOADA(k0) do{ \
        if ((k0) < C){ \
            _Pragma("unroll") \
            for (int it = 0; it < 8; it++) \
                fA[it] = x[(size_t)b*C*NPT + (size_t)((k0)+(tid>>6)+it*4)*NPT + n0 + (tid&63)]; \
        } else { \
            _Pragma("unroll") \
            for (int it = 0; it < 8; it++) \
                fA[it] = g_av[(size_t)(r0+(tid>>5)+it*8)*C + ((k0)-C) + (tid&31)]; \
        } } while(0)
    #define HG_LOADW(k0) do{ \
        _Pragma("unroll") \
        for (int it = 0; it < 8; it++) \
            fW[it] = g_Wh[(size_t)(oc0+(tid>>5)+it*8)*C2 + (k0) + (tid&31)]; } while(0)
    #define HG_STORE(k0) do{ \
        if ((k0) < C){ \
            _Pragma("unroll") \
            for (int it = 0; it < 8; it++) As[(tid>>6)+it*4][tid&63] = fA[it]; \
        } else { \
            _Pragma("unroll") \
            for (int it = 0; it < 8; it++) As[tid&31][(tid>>5)+it*8] = fA[it]; \
        } \
        _Pragma("unroll") \
        for (int it = 0; it < 8; it++) Ws[tid&31][(tid>>5)+it*8] = fW[it]; } while(0)

    HG_LOADA(0); HG_LOADW(0);
    #pragma unroll
    for (int kc = 0; kc < 8; kc++){
        int k0 = kc*32;
        __syncthreads();
        HG_STORE(k0);
        if (kc < 7){ HG_LOADA(k0+32); HG_LOADW(k0+32); }
        __syncthreads();
        #pragma unroll
        for (int kk = 0; kk < 32; kk++){
            float4 a4 = *(const float4*)&As[kk][ty*4];
            float4 w4 = *(const float4*)&Ws[kk][tx*4];
            float a[4] = {a4.x,a4.y,a4.z,a4.w};
            float w[4] = {w4.x,w4.y,w4.z,w4.w};
            #pragma unroll
            for (int i = 0; i < 4; i++)
                #pragma unroll
                for (int j = 0; j < 4; j++)
                    acc[i][j] = fmaf(a[i], w[j], acc[i][j]);
        }
    }
    #undef HG_LOADA
    #undef HG_LOADW
    #undef HG_STORE

    float hs[4] = {}, hq[4] = {};
    #pragma unroll
    for (int i = 0; i < 4; i++){
        int r = r0 + ty*4 + i;
        #pragma unroll
        for (int j = 0; j < 4; j++){
            int oc = oc0 + tx*4 + j;
            float hv = acc[i][j] + g_bh[oc];
            g_h[(size_t)r*C2 + oc] = hv;
            hs[j] += hv; hq[j] = fmaf(hv, hv, hq[j]);
        }
    }
    #pragma unroll
    for (int j = 0; j < 4; j++){
        atomicAdd(&cs[tx*4+j], hs[j]);
        atomicAdd(&cq[tx*4+j], hq[j]);
    }
    __syncthreads();
    if (tid < 64){
        atomicAdd(&g_sum[oc0 + tid],   cs[tid]);
        atomicAdd(&g_sumsq[oc0 + tid], cq[tid]);
    }
}

// ---------------- K5d: out = x + w2 @ relu(bn(h)) + b2  (64x32 tiles, 256 blocks) ----------------
__global__ __launch_bounds__(256) void k_out(const float* __restrict__ x,
                                             const float* __restrict__ w2,
                                             const float* __restrict__ b2,
                                             const float* __restrict__ gamma,
                                             const float* __restrict__ beta,
                                             float* __restrict__ out){
    __shared__ float As[32][68], Ws[32][36];
    __shared__ float ssc[C2], ssh[C2];
    int r0 = blockIdx.x*64, c0 = blockIdx.y*32;
    int b = r0 / NPT, n0 = r0 % NPT;
    int tid = threadIdx.x, tx = tid & 15, ty = tid >> 4;
    {
        int oc = tid;
        float inv = 1.f / (float)(BB*NPT);
        float mean = g_sum[oc] * inv;
        float var  = g_sumsq[oc] * inv - mean*mean;
        float rstd = rsqrtf(var + 1e-5f);
        float sc = rstd * gamma[oc];
        ssc[oc] = sc;
        ssh[oc] = beta[oc] - mean * sc;
    }
    __syncthreads();

    float acc[4][2] = {};
    float fH[8], fW[4];

    #define KO_LOAD(k0) do{ \
        _Pragma("unroll") \
        for (int it = 0; it < 8; it++) \
            fH[it] = g_h[(size_t)(r0+(tid>>5)+it*8)*C2 + (k0) + (tid&31)]; \
        _Pragma("unroll") \
        for (int it = 0; it < 4; it++) \
            fW[it] = w2[(size_t)(c0+(tid>>5)+it*8)*C2 + (k0) + (tid&31)]; } while(0)
    #define KO_STORE(k0) do{ \
        int kk = tid & 31; \
        float sc = ssc[(k0)+kk], sh = ssh[(k0)+kk]; \
        _Pragma("unroll") \
        for (int it = 0; it < 8; it++) \
            As[kk][(tid>>5)+it*8] = fmaxf(fmaf(fH[it], sc, sh), 0.f); \
        _Pragma("unroll") \
        for (int it = 0; it < 4; it++) \
            Ws[kk][(tid>>5)+it*8] = fW[it]; } while(0)

    KO_LOAD(0);
    #pragma unroll
    for (int kc = 0; kc < 8; kc++){
        int k0 = kc*32;
        __syncthreads();
        KO_STORE(k0);
        if (kc < 7) KO_LOAD(k0+32);
        __syncthreads();
        #pragma unroll
        for (int kk = 0; kk < 32; kk++){
            float4 a4 = *(const float4*)&As[kk][ty*4];
            float2 w2v = *(const float2*)&Ws[kk][tx*2];
            float a[4] = {a4.x,a4.y,a4.z,a4.w};
            #pragma unroll
            for (int i = 0; i < 4; i++){
                acc[i][0] = fmaf(a[i], w2v.x, acc[i][0]);
                acc[i][1] = fmaf(a[i], w2v.y, acc[i][1]);
            }
        }
    }
    #undef KO_LOAD
    #undef KO_STORE

    #pragma unroll
    for (int i = 0; i < 4; i++){
        int n = n0 + ty*4 + i;
        #pragma unroll
        for (int j = 0; j < 2; j++){
            int c = c0 + tx*2 + j;
            size_t idx = (size_t)b*C*NPT + (size_t)c*NPT + n;
            out[idx] = x[idx] + b2[c] + acc[i][j];
        }
    }
}

// ---------------- launch ----------------
extern "C" void kernel_launch(void* const* d_in, const int* in_sizes, int n_in,
                              void* d_out, int out_size){
    const float* x     = (const float*)d_in[0];
    const float* wq    = (const float*)d_in[1];
    const float* bq    = (const float*)d_in[2];
    const float* wk    = (const float*)d_in[3];
    const float* bk    = (const float*)d_in[4];
    const float* wv    = (const float*)d_in[5];
    const float* bv    = (const float*)d_in[6];
    const float* wm    = (const float*)d_in[7];
    const float* bm    = (const float*)d_in[8];
    const float* w1    = (const float*)d_in[9];
    const float* b1    = (const float*)d_in[10];
    const float* gamma = (const float*)d_in[11];
    const float* beta  = (const float*)d_in[12];
    const float* w2    = (const float*)d_in[13];
    const float* b2    = (const float*)d_in[14];
    float* out = (float*)d_out;

    k_gram<<<GRAM_BLKS, 256>>>(x);
    k_fusedB<<<FUSEB_BLKS, 256>>>(x, wq, bq, wk, bk, wv, bv, w1, b1, wm, bm);
    k_attn<<<BB*NPT, 128>>>();
    k_hgemm<<<dim3((BB*NPT)/64, C2/64), 256>>>(x);
    k_out<<<dim3((BB*NPT)/64, C/32), 256>>>(x, w2, b2, gamma, beta, out);
}